// round 2
// baseline (speedup 1.0000x reference)
#include <cuda_runtime.h>

// ---------------------------------------------------------------------------
// bPC SNN: 25 steps of predictive-coding spiking network dynamics.
// Layers [1024, 4096, 4096, 4096, 512], batch 512, fp32.
//
// Strategy (round 1 baseline):
//   - Generic fp32 SIMT GEMM (128x128 tile, BK=16, 8x8/thread) with fused
//     epilogue:  out = alpha*(A @ op(B)) + g0*aux0 + g1*aux1
//   - Error tensors eg0..eg3, ed1..ed4 live directly inside d_out with row
//     stride 26112 (the required concat layout) -> zero-cost output.
//   - x_data@V0^T and y@W3^T are step-invariant -> precomputed once per
//     launch; ed1/eg3 updates fold into the elementwise LIF kernel.
//   - All scratch in __device__ globals (allocation-free, graph-capturable).
// ---------------------------------------------------------------------------

#define S_LAYER (512 * 4096)
#define OUT_LD  26112          // 1024 + 3*4096 + 3*4096 + 512

__device__ float g_state[9 * S_LAYER];   // j1,j2,j3 | v1,v2,v3 | x1,x2,x3
__device__ float g_tin[3 * S_LAYER];     // injected currents, layers 1..3
__device__ float g_c1h[S_LAYER];         // 0.5 * x_data @ V0^T  (constant per launch)
__device__ float g_c2h[S_LAYER];         // 0.5 * y_target @ W3^T (constant per launch)

// ---------------------------------------------------------------------------
// GEMM: C[M,N] = alpha * A[M,K] @ op(B) + g0*aux0 + g1*aux1
//   TB=false: op(B) = B,  B is (K,N) row-major, ldb
//   TB=true : op(B) = B^T, B is (N,K) row-major, ldb
// M,N multiples of 128; K multiple of 16. All row strides in elements.
// ---------------------------------------------------------------------------

struct GemmP {
    const float* A; int lda;
    const float* B; int ldb;
    float*       C; int ldc;
    const float* aux0; int ld0; float g0;
    const float* aux1; int ld1; float g1;
    float alpha;
    int K;
};

constexpr int BM = 128, BN = 128, BK = 16, TM = 8, TN = 8;

template <bool TB>
__global__ __launch_bounds__(256, 2) void gemm_k(GemmP p) {
    __shared__ float As[BK][BM];
    __shared__ float Bs[BK][BN];

    const int tid = threadIdx.x;
    const int bm = blockIdx.y * BM;
    const int bn = blockIdx.x * BN;
    const int ty = tid >> 4;      // 0..15
    const int tx = tid & 15;      // 0..15

    float acc[TM][TN];
#pragma unroll
    for (int i = 0; i < TM; i++)
#pragma unroll
        for (int j = 0; j < TN; j++) acc[i][j] = 0.0f;

    // loader indices: K-major tiles (A always; B when TB)
    const int arow = tid >> 2;          // 0..63
    const int acol = (tid & 3) << 2;    // 0,4,8,12
    // loader indices for B when !TB (N-major rows)
    const int brow = tid >> 5;          // 0..7
    const int bcol = (tid & 31) << 2;   // 0..124

    for (int k0 = 0; k0 < p.K; k0 += BK) {
        // --- load A tile (128 x 16), transpose into As[k][m] ---
#pragma unroll
        for (int r = 0; r < 2; r++) {
            const int m = arow + 64 * r;
            const float4 a = *reinterpret_cast<const float4*>(
                p.A + (long)(bm + m) * p.lda + k0 + acol);
            As[acol + 0][m] = a.x;
            As[acol + 1][m] = a.y;
            As[acol + 2][m] = a.z;
            As[acol + 3][m] = a.w;
        }
        // --- load B tile ---
        if (TB) {
#pragma unroll
            for (int r = 0; r < 2; r++) {
                const int n = arow + 64 * r;
                const float4 b = *reinterpret_cast<const float4*>(
                    p.B + (long)(bn + n) * p.ldb + k0 + acol);
                Bs[acol + 0][n] = b.x;
                Bs[acol + 1][n] = b.y;
                Bs[acol + 2][n] = b.z;
                Bs[acol + 3][n] = b.w;
            }
        } else {
#pragma unroll
            for (int r = 0; r < 2; r++) {
                const int k = brow + 8 * r;
                *reinterpret_cast<float4*>(&Bs[k][bcol]) =
                    *reinterpret_cast<const float4*>(
                        p.B + (long)(k0 + k) * p.ldb + bn + bcol);
            }
        }
        __syncthreads();

#pragma unroll
        for (int kk = 0; kk < BK; kk++) {
            float af[TM], bf[TN];
            *reinterpret_cast<float4*>(af)     = *reinterpret_cast<float4*>(&As[kk][ty * 8]);
            *reinterpret_cast<float4*>(af + 4) = *reinterpret_cast<float4*>(&As[kk][ty * 8 + 4]);
            *reinterpret_cast<float4*>(bf)     = *reinterpret_cast<float4*>(&Bs[kk][tx * 8]);
            *reinterpret_cast<float4*>(bf + 4) = *reinterpret_cast<float4*>(&Bs[kk][tx * 8 + 4]);
#pragma unroll
            for (int i = 0; i < TM; i++)
#pragma unroll
                for (int j = 0; j < TN; j++) acc[i][j] += af[i] * bf[j];
        }
        __syncthreads();
    }

    // --- epilogue ---
#pragma unroll
    for (int i = 0; i < TM; i++) {
        const int row = bm + ty * 8 + i;
        const int col = bn + tx * 8;
#pragma unroll
        for (int j = 0; j < TN; j++) {
            float v = p.alpha * acc[i][j];
            if (p.aux0) v += p.g0 * p.aux0[(long)row * p.ld0 + col + j];
            if (p.aux1) v += p.g1 * p.aux1[(long)row * p.ld1 + col + j];
            p.C[(long)row * p.ldc + col + j] = v;
        }
    }
}

// ---------------------------------------------------------------------------
// LIF elementwise update for layers 1..3, also emits ed1 and eg3 (which need
// only the precomputed constants + fresh x).
// ---------------------------------------------------------------------------
__global__ void lif_k(float* dout) {
    const long idx = (long)blockIdx.x * blockDim.x + threadIdx.x;
    if (idx >= 3L * S_LAYER) return;
    const int L = (int)(idx / S_LAYER);          // 0..2 -> layers 1..3
    const int r = (int)(idx - (long)L * S_LAYER);

    const float tin = g_tin[idx];
    float j = g_state[idx];
    float v = g_state[3L * S_LAYER + idx];
    float x = g_state[6L * S_LAYER + idx];

    j = j + 0.25f * (tin - j);                    // dt/tau_j = 0.25, kappa=1
    v = v + 0.05f * (j - v);                      // dt/tau_m = 0.05, gamma=R=1
    const float spk = (v > 1.0f) ? 1.0f : 0.0f;
    v = v * (1.0f - spk);
    x = x * (1.0f - 0.025f) + spk;                // dt/tau_tr = 0.025

    g_state[idx] = j;
    g_state[3L * S_LAYER + idx] = v;
    g_state[6L * S_LAYER + idx] = x;

    if (L == 0) {                                 // ed1 = 0.5*x1 - 0.5*x_data@V0^T
        const int b = r >> 12, f = r & 4095;
        dout[(long)b * OUT_LD + 13312 + f] = 0.5f * x - g_c1h[r];
    } else if (L == 2) {                          // eg3 = 0.5*x3 - 0.5*y@W3^T
        const int b = r >> 12, f = r & 4095;
        dout[(long)b * OUT_LD + 9216 + f] = 0.5f * x - g_c2h[r];
    }
}

__global__ void zero_k(float* dout) {
    const long n1 = 9L * S_LAYER;
    const long n2 = 512L * OUT_LD;
    for (long i = (long)blockIdx.x * blockDim.x + threadIdx.x; i < n1 + n2;
         i += (long)gridDim.x * blockDim.x) {
        if (i < n1) g_state[i] = 0.0f;
        else        dout[i - n1] = 0.0f;
    }
}

// ---------------------------------------------------------------------------
static void gemm(bool tb, const float* A, int lda, const float* B, int ldb,
                 float* C, int ldc,
                 const float* a0, int l0, float g0,
                 const float* a1, int l1, float g1,
                 float alpha, int M, int N, int K) {
    GemmP p;
    p.A = A; p.lda = lda; p.B = B; p.ldb = ldb; p.C = C; p.ldc = ldc;
    p.aux0 = a0; p.ld0 = l0; p.g0 = g0;
    p.aux1 = a1; p.ld1 = l1; p.g1 = g1;
    p.alpha = alpha; p.K = K;
    dim3 grid(N / BN, M / BM);
    if (tb) gemm_k<true><<<grid, 256>>>(p);
    else    gemm_k<false><<<grid, 256>>>(p);
}

extern "C" void kernel_launch(void* const* d_in, const int* in_sizes, int n_in,
                              void* d_out, int out_size) {
    (void)in_sizes; (void)n_in; (void)out_size;
    // setup_inputs() dict order: x_data, y_target, W0, V0, W1, V1, W2, V2, W3, V3, num_steps
    const float* xd = (const float*)d_in[0];   // (512, 1024)
    const float* yt = (const float*)d_in[1];   // (512, 512)
    const float* W0 = (const float*)d_in[2];   // (1024, 4096)
    const float* V0 = (const float*)d_in[3];   // (4096, 1024)
    const float* W1 = (const float*)d_in[4];   // (4096, 4096)
    const float* V1 = (const float*)d_in[5];   // (4096, 4096)
    const float* W2 = (const float*)d_in[6];   // (4096, 4096)
    const float* V2 = (const float*)d_in[7];   // (4096, 4096)
    const float* W3 = (const float*)d_in[8];   // (4096, 512)
    const float* V3 = (const float*)d_in[9];   // (512, 4096)
    float* out = (float*)d_out;                // (512, 26112)

    float *st = nullptr, *tin = nullptr, *c1h = nullptr, *c2h = nullptr;
    cudaGetSymbolAddress((void**)&st,  g_state);
    cudaGetSymbolAddress((void**)&tin, g_tin);
    cudaGetSymbolAddress((void**)&c1h, g_c1h);
    cudaGetSymbolAddress((void**)&c2h, g_c2h);

    float* x1 = st + 6L * S_LAYER;
    float* x2 = st + 7L * S_LAYER;
    float* x3 = st + 8L * S_LAYER;
    float* t1 = tin;
    float* t2 = tin + S_LAYER;
    float* t3 = tin + 2L * S_LAYER;

    // error-tensor slices inside d_out (row stride OUT_LD)
    float* eg0 = out + 0;
    float* eg1 = out + 1024;
    float* eg2 = out + 5120;
    float* eg3 = out + 9216;    (void)eg3;  // written by lif_k
    float* ed1 = out + 13312;               // written by lif_k
    float* ed2 = out + 17408;
    float* ed3 = out + 21504;
    float* ed4 = out + 25600;

    // --- init: zero state + all error signals ---
    zero_k<<<2048, 256>>>(out);

    // --- step-invariant terms ---
    // c1h = 0.5 * x_data @ V0^T   (M=512,N=4096,K=1024)
    gemm(true, xd, 1024, V0, 1024, c1h, 4096,
         nullptr, 0, 0.f, nullptr, 0, 0.f, 0.5f, 512, 4096, 1024);
    // c2h = 0.5 * y_target @ W3^T (M=512,N=4096,K=512)
    gemm(true, yt, 512, W3, 512, c2h, 4096,
         nullptr, 0, 0.f, nullptr, 0, 0.f, 0.5f, 512, 4096, 512);

    const int NUM_STEPS = 25;
    for (int t = 0; t < NUM_STEPS; t++) {
        // ---------------- Phase A: injected currents ----------------
        // t1 = eg0@W0 - ed1 - eg1 ; t1 += ed2@V1
        gemm(false, eg0, OUT_LD, W0, 4096, t1, 4096,
             ed1, OUT_LD, -1.f, eg1, OUT_LD, -1.f, 1.f, 512, 4096, 1024);
        gemm(false, ed2, OUT_LD, V1, 4096, t1, 4096,
             t1, 4096, 1.f, nullptr, 0, 0.f, 1.f, 512, 4096, 4096);
        // t2 = eg1@W1 - ed2 - eg2 ; t2 += ed3@V2
        gemm(false, eg1, OUT_LD, W1, 4096, t2, 4096,
             ed2, OUT_LD, -1.f, eg2, OUT_LD, -1.f, 1.f, 512, 4096, 4096);
        gemm(false, ed3, OUT_LD, V2, 4096, t2, 4096,
             t2, 4096, 1.f, nullptr, 0, 0.f, 1.f, 512, 4096, 4096);
        // t3 = eg2@W2 - ed3 - eg3 ; t3 += ed4@V3
        gemm(false, eg2, OUT_LD, W2, 4096, t3, 4096,
             ed3, OUT_LD, -1.f, eg3, OUT_LD, -1.f, 1.f, 512, 4096, 4096);
        gemm(false, ed4, OUT_LD, V3, 4096, t3, 4096,
             t3, 4096, 1.f, nullptr, 0, 0.f, 1.f, 512, 4096, 512);

        // ---------------- LIF update (+ ed1, eg3) ----------------
        lif_k<<<(3 * S_LAYER + 255) / 256, 256>>>(out);

        // ---------------- Phase B: error signals ----------------
        // eg0 = 0.5*x_data - 0.5*(x1 @ W0^T)        (N=1024,K=4096)
        gemm(true, x1, 4096, W0, 4096, eg0, OUT_LD,
             xd, 1024, 0.5f, nullptr, 0, 0.f, -0.5f, 512, 1024, 4096);
        // eg1 = 0.5*x1 - 0.5*(x2 @ W1^T)
        gemm(true, x2, 4096, W1, 4096, eg1, OUT_LD,
             x1, 4096, 0.5f, nullptr, 0, 0.f, -0.5f, 512, 4096, 4096);
        // ed2 = 0.5*x2 - 0.5*(x1 @ V1^T)
        gemm(true, x1, 4096, V1, 4096, ed2, OUT_LD,
             x2, 4096, 0.5f, nullptr, 0, 0.f, -0.5f, 512, 4096, 4096);
        // eg2 = 0.5*x2 - 0.5*(x3 @ W2^T)
        gemm(true, x3, 4096, W2, 4096, eg2, OUT_LD,
             x2, 4096, 0.5f, nullptr, 0, 0.f, -0.5f, 512, 4096, 4096);
        // ed3 = 0.5*x3 - 0.5*(x2 @ V2^T)
        gemm(true, x2, 4096, V2, 4096, ed3, OUT_LD,
             x3, 4096, 0.5f, nullptr, 0, 0.f, -0.5f, 512, 4096, 4096);
        // ed4 = 0.5*y - 0.5*(x3 @ V3^T)             (N=512,K=4096)
        gemm(true, x3, 4096, V3, 4096, ed4, OUT_LD,
             yt, 512, 0.5f, nullptr, 0, 0.f, -0.5f, 512, 512, 4096);
    }
}

// round 4
// speedup vs baseline: 1.0007x; 1.0007x over previous
#include <cuda_runtime.h>

// ---------------------------------------------------------------------------
// bPC SNN: 25 steps of predictive-coding spiking network dynamics.
// Layers [1024, 4096, 4096, 4096, 512], batch 512, fp32.
//
// Strategy (round 1 baseline):
//   - Generic fp32 SIMT GEMM (128x128 tile, BK=16, 8x8/thread) with fused
//     epilogue:  out = alpha*(A @ op(B)) + g0*aux0 + g1*aux1
//   - Error tensors eg0..eg3, ed1..ed4 live directly inside d_out with row
//     stride 26112 (the required concat layout) -> zero-cost output.
//   - x_data@V0^T and y@W3^T are step-invariant -> precomputed once per
//     launch; ed1/eg3 updates fold into the elementwise LIF kernel.
//   - All scratch in __device__ globals (allocation-free, graph-capturable).
// ---------------------------------------------------------------------------

#define S_LAYER (512 * 4096)
#define OUT_LD  26112          // 1024 + 3*4096 + 3*4096 + 512

__device__ float g_state[9 * S_LAYER];   // j1,j2,j3 | v1,v2,v3 | x1,x2,x3
__device__ float g_tin[3 * S_LAYER];     // injected currents, layers 1..3
__device__ float g_c1h[S_LAYER];         // 0.5 * x_data @ V0^T  (constant per launch)
__device__ float g_c2h[S_LAYER];         // 0.5 * y_target @ W3^T (constant per launch)

// ---------------------------------------------------------------------------
// GEMM: C[M,N] = alpha * A[M,K] @ op(B) + g0*aux0 + g1*aux1
//   TB=false: op(B) = B,  B is (K,N) row-major, ldb
//   TB=true : op(B) = B^T, B is (N,K) row-major, ldb
// M,N multiples of 128; K multiple of 16. All row strides in elements.
// ---------------------------------------------------------------------------

struct GemmP {
    const float* A; int lda;
    const float* B; int ldb;
    float*       C; int ldc;
    const float* aux0; int ld0; float g0;
    const float* aux1; int ld1; float g1;
    float alpha;
    int K;
};

constexpr int BM = 128, BN = 128, BK = 16, TM = 8, TN = 8;

template <bool TB>
__global__ __launch_bounds__(256, 2) void gemm_k(GemmP p) {
    __shared__ float As[BK][BM];
    __shared__ float Bs[BK][BN];

    const int tid = threadIdx.x;
    const int bm = blockIdx.y * BM;
    const int bn = blockIdx.x * BN;
    const int ty = tid >> 4;      // 0..15
    const int tx = tid & 15;      // 0..15

    float acc[TM][TN];
#pragma unroll
    for (int i = 0; i < TM; i++)
#pragma unroll
        for (int j = 0; j < TN; j++) acc[i][j] = 0.0f;

    // loader indices: K-major tiles (A always; B when TB)
    const int arow = tid >> 2;          // 0..63
    const int acol = (tid & 3) << 2;    // 0,4,8,12
    // loader indices for B when !TB (N-major rows)
    const int brow = tid >> 5;          // 0..7
    const int bcol = (tid & 31) << 2;   // 0..124

    for (int k0 = 0; k0 < p.K; k0 += BK) {
        // --- load A tile (128 x 16), transpose into As[k][m] ---
#pragma unroll
        for (int r = 0; r < 2; r++) {
            const int m = arow + 64 * r;
            const float4 a = *reinterpret_cast<const float4*>(
                p.A + (long)(bm + m) * p.lda + k0 + acol);
            As[acol + 0][m] = a.x;
            As[acol + 1][m] = a.y;
            As[acol + 2][m] = a.z;
            As[acol + 3][m] = a.w;
        }
        // --- load B tile ---
        if (TB) {
#pragma unroll
            for (int r = 0; r < 2; r++) {
                const int n = arow + 64 * r;
                const float4 b = *reinterpret_cast<const float4*>(
                    p.B + (long)(bn + n) * p.ldb + k0 + acol);
                Bs[acol + 0][n] = b.x;
                Bs[acol + 1][n] = b.y;
                Bs[acol + 2][n] = b.z;
                Bs[acol + 3][n] = b.w;
            }
        } else {
#pragma unroll
            for (int r = 0; r < 2; r++) {
                const int k = brow + 8 * r;
                *reinterpret_cast<float4*>(&Bs[k][bcol]) =
                    *reinterpret_cast<const float4*>(
                        p.B + (long)(k0 + k) * p.ldb + bn + bcol);
            }
        }
        __syncthreads();

#pragma unroll
        for (int kk = 0; kk < BK; kk++) {
            float af[TM], bf[TN];
            *reinterpret_cast<float4*>(af)     = *reinterpret_cast<float4*>(&As[kk][ty * 8]);
            *reinterpret_cast<float4*>(af + 4) = *reinterpret_cast<float4*>(&As[kk][ty * 8 + 4]);
            *reinterpret_cast<float4*>(bf)     = *reinterpret_cast<float4*>(&Bs[kk][tx * 8]);
            *reinterpret_cast<float4*>(bf + 4) = *reinterpret_cast<float4*>(&Bs[kk][tx * 8 + 4]);
#pragma unroll
            for (int i = 0; i < TM; i++)
#pragma unroll
                for (int j = 0; j < TN; j++) acc[i][j] += af[i] * bf[j];
        }
        __syncthreads();
    }

    // --- epilogue ---
#pragma unroll
    for (int i = 0; i < TM; i++) {
        const int row = bm + ty * 8 + i;
        const int col = bn + tx * 8;
#pragma unroll
        for (int j = 0; j < TN; j++) {
            float v = p.alpha * acc[i][j];
            if (p.aux0) v += p.g0 * p.aux0[(long)row * p.ld0 + col + j];
            if (p.aux1) v += p.g1 * p.aux1[(long)row * p.ld1 + col + j];
            p.C[(long)row * p.ldc + col + j] = v;
        }
    }
}

// ---------------------------------------------------------------------------
// LIF elementwise update for layers 1..3, also emits ed1 and eg3 (which need
// only the precomputed constants + fresh x).
// ---------------------------------------------------------------------------
__global__ void lif_k(float* dout) {
    const long idx = (long)blockIdx.x * blockDim.x + threadIdx.x;
    if (idx >= 3L * S_LAYER) return;
    const int L = (int)(idx / S_LAYER);          // 0..2 -> layers 1..3
    const int r = (int)(idx - (long)L * S_LAYER);

    const float tin = g_tin[idx];
    float j = g_state[idx];
    float v = g_state[3L * S_LAYER + idx];
    float x = g_state[6L * S_LAYER + idx];

    j = j + 0.25f * (tin - j);                    // dt/tau_j = 0.25, kappa=1
    v = v + 0.05f * (j - v);                      // dt/tau_m = 0.05, gamma=R=1
    const float spk = (v > 1.0f) ? 1.0f : 0.0f;
    v = v * (1.0f - spk);
    x = x * (1.0f - 0.025f) + spk;                // dt/tau_tr = 0.025

    g_state[idx] = j;
    g_state[3L * S_LAYER + idx] = v;
    g_state[6L * S_LAYER + idx] = x;

    if (L == 0) {                                 // ed1 = 0.5*x1 - 0.5*x_data@V0^T
        const int b = r >> 12, f = r & 4095;
        dout[(long)b * OUT_LD + 13312 + f] = 0.5f * x - g_c1h[r];
    } else if (L == 2) {                          // eg3 = 0.5*x3 - 0.5*y@W3^T
        const int b = r >> 12, f = r & 4095;
        dout[(long)b * OUT_LD + 9216 + f] = 0.5f * x - g_c2h[r];
    }
}

__global__ void zero_k(float* dout) {
    const long n1 = 9L * S_LAYER;
    const long n2 = 512L * OUT_LD;
    for (long i = (long)blockIdx.x * blockDim.x + threadIdx.x; i < n1 + n2;
         i += (long)gridDim.x * blockDim.x) {
        if (i < n1) g_state[i] = 0.0f;
        else        dout[i - n1] = 0.0f;
    }
}

// ---------------------------------------------------------------------------
static void gemm(bool tb, const float* A, int lda, const float* B, int ldb,
                 float* C, int ldc,
                 const float* a0, int l0, float g0,
                 const float* a1, int l1, float g1,
                 float alpha, int M, int N, int K) {
    GemmP p;
    p.A = A; p.lda = lda; p.B = B; p.ldb = ldb; p.C = C; p.ldc = ldc;
    p.aux0 = a0; p.ld0 = l0; p.g0 = g0;
    p.aux1 = a1; p.ld1 = l1; p.g1 = g1;
    p.alpha = alpha; p.K = K;
    dim3 grid(N / BN, M / BM);
    if (tb) gemm_k<true><<<grid, 256>>>(p);
    else    gemm_k<false><<<grid, 256>>>(p);
}

extern "C" void kernel_launch(void* const* d_in, const int* in_sizes, int n_in,
                              void* d_out, int out_size) {
    (void)in_sizes; (void)n_in; (void)out_size;
    // setup_inputs() dict order: x_data, y_target, W0, V0, W1, V1, W2, V2, W3, V3, num_steps
    const float* xd = (const float*)d_in[0];   // (512, 1024)
    const float* yt = (const float*)d_in[1];   // (512, 512)
    const float* W0 = (const float*)d_in[2];   // (1024, 4096)
    const float* V0 = (const float*)d_in[3];   // (4096, 1024)
    const float* W1 = (const float*)d_in[4];   // (4096, 4096)
    const float* V1 = (const float*)d_in[5];   // (4096, 4096)
    const float* W2 = (const float*)d_in[6];   // (4096, 4096)
    const float* V2 = (const float*)d_in[7];   // (4096, 4096)
    const float* W3 = (const float*)d_in[8];   // (4096, 512)
    const float* V3 = (const float*)d_in[9];   // (512, 4096)
    float* out = (float*)d_out;                // (512, 26112)

    float *st = nullptr, *tin = nullptr, *c1h = nullptr, *c2h = nullptr;
    cudaGetSymbolAddress((void**)&st,  g_state);
    cudaGetSymbolAddress((void**)&tin, g_tin);
    cudaGetSymbolAddress((void**)&c1h, g_c1h);
    cudaGetSymbolAddress((void**)&c2h, g_c2h);

    float* x1 = st + 6L * S_LAYER;
    float* x2 = st + 7L * S_LAYER;
    float* x3 = st + 8L * S_LAYER;
    float* t1 = tin;
    float* t2 = tin + S_LAYER;
    float* t3 = tin + 2L * S_LAYER;

    // error-tensor slices inside d_out (row stride OUT_LD)
    float* eg0 = out + 0;
    float* eg1 = out + 1024;
    float* eg2 = out + 5120;
    float* eg3 = out + 9216;    (void)eg3;  // written by lif_k
    float* ed1 = out + 13312;               // written by lif_k
    float* ed2 = out + 17408;
    float* ed3 = out + 21504;
    float* ed4 = out + 25600;

    // --- init: zero state + all error signals ---
    zero_k<<<2048, 256>>>(out);

    // --- step-invariant terms ---
    // c1h = 0.5 * x_data @ V0^T   (M=512,N=4096,K=1024)
    gemm(true, xd, 1024, V0, 1024, c1h, 4096,
         nullptr, 0, 0.f, nullptr, 0, 0.f, 0.5f, 512, 4096, 1024);
    // c2h = 0.5 * y_target @ W3^T (M=512,N=4096,K=512)
    gemm(true, yt, 512, W3, 512, c2h, 4096,
         nullptr, 0, 0.f, nullptr, 0, 0.f, 0.5f, 512, 4096, 512);

    const int NUM_STEPS = 25;
    for (int t = 0; t < NUM_STEPS; t++) {
        // ---------------- Phase A: injected currents ----------------
        // t1 = eg0@W0 - ed1 - eg1 ; t1 += ed2@V1
        gemm(false, eg0, OUT_LD, W0, 4096, t1, 4096,
             ed1, OUT_LD, -1.f, eg1, OUT_LD, -1.f, 1.f, 512, 4096, 1024);
        gemm(false, ed2, OUT_LD, V1, 4096, t1, 4096,
             t1, 4096, 1.f, nullptr, 0, 0.f, 1.f, 512, 4096, 4096);
        // t2 = eg1@W1 - ed2 - eg2 ; t2 += ed3@V2
        gemm(false, eg1, OUT_LD, W1, 4096, t2, 4096,
             ed2, OUT_LD, -1.f, eg2, OUT_LD, -1.f, 1.f, 512, 4096, 4096);
        gemm(false, ed3, OUT_LD, V2, 4096, t2, 4096,
             t2, 4096, 1.f, nullptr, 0, 0.f, 1.f, 512, 4096, 4096);
        // t3 = eg2@W2 - ed3 - eg3 ; t3 += ed4@V3
        gemm(false, eg2, OUT_LD, W2, 4096, t3, 4096,
             ed3, OUT_LD, -1.f, eg3, OUT_LD, -1.f, 1.f, 512, 4096, 4096);
        gemm(false, ed4, OUT_LD, V3, 4096, t3, 4096,
             t3, 4096, 1.f, nullptr, 0, 0.f, 1.f, 512, 4096, 512);

        // ---------------- LIF update (+ ed1, eg3) ----------------
        lif_k<<<(3 * S_LAYER + 255) / 256, 256>>>(out);

        // ---------------- Phase B: error signals ----------------
        // eg0 = 0.5*x_data - 0.5*(x1 @ W0^T)        (N=1024,K=4096)
        gemm(true, x1, 4096, W0, 4096, eg0, OUT_LD,
             xd, 1024, 0.5f, nullptr, 0, 0.f, -0.5f, 512, 1024, 4096);
        // eg1 = 0.5*x1 - 0.5*(x2 @ W1^T)
        gemm(true, x2, 4096, W1, 4096, eg1, OUT_LD,
             x1, 4096, 0.5f, nullptr, 0, 0.f, -0.5f, 512, 4096, 4096);
        // ed2 = 0.5*x2 - 0.5*(x1 @ V1^T)
        gemm(true, x1, 4096, V1, 4096, ed2, OUT_LD,
             x2, 4096, 0.5f, nullptr, 0, 0.f, -0.5f, 512, 4096, 4096);
        // eg2 = 0.5*x2 - 0.5*(x3 @ W2^T)
        gemm(true, x3, 4096, W2, 4096, eg2, OUT_LD,
             x2, 4096, 0.5f, nullptr, 0, 0.f, -0.5f, 512, 4096, 4096);
        // ed3 = 0.5*x3 - 0.5*(x2 @ V2^T)
        gemm(true, x2, 4096, V2, 4096, ed3, OUT_LD,
             x3, 4096, 0.5f, nullptr, 0, 0.f, -0.5f, 512, 4096, 4096);
        // ed4 = 0.5*y - 0.5*(x3 @ V3^T)             (N=512,K=4096)
        gemm(true, x3, 4096, V3, 4096, ed4, OUT_LD,
             yt, 512, 0.5f, nullptr, 0, 0.f, -0.5f, 512, 512, 4096);
    }
}

// round 5
// speedup vs baseline: 1.2327x; 1.2318x over previous
#include <cuda_runtime.h>

// ---------------------------------------------------------------------------
// bPC SNN: 25 steps of predictive-coding spiking network dynamics.
// Layers [1024, 4096, 4096, 4096, 512], batch 512, fp32.
//
// Round-5 strategy:
//   - Pipelined fp32 SIMT GEMM: 128x128 tile, BK=16, 256 thr, 8x8/thread,
//     double-buffered smem + register-staged global prefetch + double-buffered
//     fragments. __launch_bounds__(256,1): grid (~128) < #SM (148) means
//     1 CTA/SM regardless, so spend registers on pipelining, not occupancy.
//   - Two-segment K loop: phase-A pairs  t_i = [eg_{i-1}|ed_{i+1}] @ [W;V]
//     merged into single launches (K = 5120 / 8192 / 4608).
//   - Split-K (4x / 8x) for the small-N GEMMs eg0 (N=1024) and ed4 (N=512)
//     into __device__ partial slabs + tiny reduce kernel -> 128 CTAs each.
//   - Error tensors live directly inside d_out (row stride 26112) -> the
//     final concat is free; next-step GEMMs read d_out slices as A operands.
//   - x_data@V0^T and y@W3^T are step-invariant -> precomputed; ed1/eg3 fold
//     into the elementwise LIF kernel.
// ---------------------------------------------------------------------------

#define S_LAYER (512 * 4096)
#define OUT_LD  26112          // 1024 + 3*4096 + 3*4096 + 512

__device__ float g_state[9 * S_LAYER];      // j1,j2,j3 | v1,v2,v3 | x1,x2,x3
__device__ float g_tin[3 * S_LAYER];        // injected currents, layers 1..3
__device__ float g_c1h[S_LAYER];            // 0.5 * x_data @ V0^T
__device__ float g_c2h[S_LAYER];            // 0.5 * y_target @ W3^T
__device__ float g_pA[4 * 512 * 1024];      // eg0 split-K partials
__device__ float g_pB[8 * 512 * 512];       // ed4 split-K partials

constexpr int BM = 128, BN = 128, BK = 16, PAD = 4;

// ---------------------------------------------------------------------------
// GEMM: C = alpha * ( A1 @ op(B1) [K1]  +  A2 @ op(B2) [K2] ) + g0*aux0 + g1*aux1
//   TB=false: op(B) = B,  B is (K,N) row-major
//   TB=true : op(B) = B^T, B is (N,K) row-major
// If kc != 0: split-K mode (single segment), blockIdx.z selects K chunk of
// length kc; C is offset by z*czstride. M,N multiples of 128; K mult of 16.
// ---------------------------------------------------------------------------

struct GemmP {
    const float* A1; int lda1;
    const float* B1; int ldb1;
    const float* A2; int lda2;
    const float* B2; int ldb2;
    int K1, K2;
    float*       C; int ldc;
    const float* aux0; int ld0; float g0;
    const float* aux1; int ld1; float g1;
    float alpha;
    int  kc;
    long czstride;
};

template <bool TB>
__global__ __launch_bounds__(256, 1) void gemm_k(GemmP p) {
    __shared__ float As[2][BK][BM + PAD];
    __shared__ float Bs[2][BK][BN + PAD];

    const int tid  = threadIdx.x;
    const int bm   = blockIdx.y * BM;
    const int bn   = blockIdx.x * BN;
    const int ty   = tid >> 4;          // 0..15
    const int tx   = tid & 15;          // 0..15
    const int arow = tid >> 2;          // 0..63
    const int acol = (tid & 3) << 2;    // 0,4,8,12
    const int brow = tid >> 5;          // 0..7
    const int bcol = (tid & 31) << 2;   // 0..124

    const float* A1 = p.A1;
    const float* B1 = p.B1;
    int    K1 = p.K1;
    float* C  = p.C;
    if (p.kc) {                         // split-K
        A1 += (long)blockIdx.z * p.kc;
        B1 += (long)blockIdx.z * p.kc;  // TB only: k-offset along B rows
        K1  = p.kc;
        C  += (long)blockIdx.z * p.czstride;
    }
    const int nk = (K1 + p.K2) / BK;

    float acc[8][8];
#pragma unroll
    for (int i = 0; i < 8; i++)
#pragma unroll
        for (int j = 0; j < 8; j++) acc[i][j] = 0.0f;

    float4 ra0, ra1, rb0, rb1;

#define LOADG(kt_) do {                                                        \
    const int k0_ = (kt_) * BK;                                                \
    const float* Ap_; int lda_; const float* Bp_; int ldb_; int ka_;           \
    if (k0_ < K1) { Ap_ = A1; lda_ = p.lda1; Bp_ = B1;  ldb_ = p.ldb1; ka_ = k0_; } \
    else { Ap_ = p.A2; lda_ = p.lda2; Bp_ = p.B2; ldb_ = p.ldb2; ka_ = k0_ - K1; }  \
    ra0 = *(const float4*)(Ap_ + (long)(bm + arow)      * lda_ + ka_ + acol);  \
    ra1 = *(const float4*)(Ap_ + (long)(bm + arow + 64) * lda_ + ka_ + acol);  \
    if (TB) {                                                                  \
        rb0 = *(const float4*)(Bp_ + (long)(bn + arow)      * ldb_ + ka_ + acol); \
        rb1 = *(const float4*)(Bp_ + (long)(bn + arow + 64) * ldb_ + ka_ + acol); \
    } else {                                                                   \
        rb0 = *(const float4*)(Bp_ + (long)(ka_ + brow)     * ldb_ + bn + bcol);  \
        rb1 = *(const float4*)(Bp_ + (long)(ka_ + brow + 8) * ldb_ + bn + bcol);  \
    }                                                                          \
} while (0)

#define STORES(buf_) do {                                                      \
    As[buf_][acol + 0][arow]      = ra0.x;                                     \
    As[buf_][acol + 1][arow]      = ra0.y;                                     \
    As[buf_][acol + 2][arow]      = ra0.z;                                     \
    As[buf_][acol + 3][arow]      = ra0.w;                                     \
    As[buf_][acol + 0][arow + 64] = ra1.x;                                     \
    As[buf_][acol + 1][arow + 64] = ra1.y;                                     \
    As[buf_][acol + 2][arow + 64] = ra1.z;                                     \
    As[buf_][acol + 3][arow + 64] = ra1.w;                                     \
    if (TB) {                                                                  \
        Bs[buf_][acol + 0][arow]      = rb0.x;                                 \
        Bs[buf_][acol + 1][arow]      = rb0.y;                                 \
        Bs[buf_][acol + 2][arow]      = rb0.z;                                 \
        Bs[buf_][acol + 3][arow]      = rb0.w;                                 \
        Bs[buf_][acol + 0][arow + 64] = rb1.x;                                 \
        Bs[buf_][acol + 1][arow + 64] = rb1.y;                                 \
        Bs[buf_][acol + 2][arow + 64] = rb1.z;                                 \
        Bs[buf_][acol + 3][arow + 64] = rb1.w;                                 \
    } else {                                                                   \
        *(float4*)&Bs[buf_][brow][bcol]     = rb0;                             \
        *(float4*)&Bs[buf_][brow + 8][bcol] = rb1;                             \
    }                                                                          \
} while (0)

    float af[2][8], bf[2][8];
#define LDFRAG(d_, buf_, kk_) do {                                             \
    *(float4*)&af[d_][0] = *(const float4*)&As[buf_][kk_][ty * 8];             \
    *(float4*)&af[d_][4] = *(const float4*)&As[buf_][kk_][ty * 8 + 4];         \
    *(float4*)&bf[d_][0] = *(const float4*)&Bs[buf_][kk_][tx * 8];             \
    *(float4*)&bf[d_][4] = *(const float4*)&Bs[buf_][kk_][tx * 8 + 4];         \
} while (0)

    LOADG(0);
    STORES(0);
    __syncthreads();

    for (int kt = 0; kt < nk; ++kt) {
        const int cur = kt & 1;
        if (kt + 1 < nk) LOADG(kt + 1);      // global prefetch (in regs)
        LDFRAG(0, cur, 0);
#pragma unroll
        for (int kk = 0; kk < BK; ++kk) {
            const int c = kk & 1;
            if (kk + 1 < BK) LDFRAG(c ^ 1, cur, kk + 1);
#pragma unroll
            for (int i = 0; i < 8; ++i)
#pragma unroll
                for (int j = 0; j < 8; ++j)
                    acc[i][j] += af[c][i] * bf[c][j];
        }
        if (kt + 1 < nk) STORES(cur ^ 1);
        __syncthreads();
    }

    // ---- epilogue ----
#pragma unroll
    for (int i = 0; i < 8; ++i) {
        const long row = bm + ty * 8 + i;
        const int  col = bn + tx * 8;
        float r[8];
#pragma unroll
        for (int j = 0; j < 8; ++j) r[j] = p.alpha * acc[i][j];
        if (p.aux0) {
            const float* a0 = p.aux0 + row * p.ld0 + col;
            const float4 u0 = *(const float4*)(a0);
            const float4 u1 = *(const float4*)(a0 + 4);
            r[0] += p.g0 * u0.x; r[1] += p.g0 * u0.y;
            r[2] += p.g0 * u0.z; r[3] += p.g0 * u0.w;
            r[4] += p.g0 * u1.x; r[5] += p.g0 * u1.y;
            r[6] += p.g0 * u1.z; r[7] += p.g0 * u1.w;
        }
        if (p.aux1) {
            const float* a1 = p.aux1 + row * p.ld1 + col;
            const float4 u0 = *(const float4*)(a1);
            const float4 u1 = *(const float4*)(a1 + 4);
            r[0] += p.g1 * u0.x; r[1] += p.g1 * u0.y;
            r[2] += p.g1 * u0.z; r[3] += p.g1 * u0.w;
            r[4] += p.g1 * u1.x; r[5] += p.g1 * u1.y;
            r[6] += p.g1 * u1.z; r[7] += p.g1 * u1.w;
        }
        *(float4*)(C + row * p.ldc + col)     = make_float4(r[0], r[1], r[2], r[3]);
        *(float4*)(C + row * p.ldc + col + 4) = make_float4(r[4], r[5], r[6], r[7]);
    }
#undef LOADG
#undef STORES
#undef LDFRAG
}

// ---------------------------------------------------------------------------
// Split-K reduce: out[b, outoff+f] = 0.5*ref[b,f] - 0.5 * sum_z P[z][b,f]
// ---------------------------------------------------------------------------
__global__ void reduce_k(const float* __restrict__ P, int nsplit,
                         const float* __restrict__ ref, int ldref,
                         float* __restrict__ out, int outoff, int N) {
    const int idx = blockIdx.x * blockDim.x + threadIdx.x;
    if (idx >= 512 * N) return;
    const int  b    = idx / N;
    const int  f    = idx - b * N;
    const long slab = (long)512 * N;
    float s = 0.0f;
    for (int z = 0; z < nsplit; ++z) s += P[z * slab + idx];
    out[(long)b * OUT_LD + outoff + f] = 0.5f * ref[(long)b * ldref + f] - 0.5f * s;
}

// ---------------------------------------------------------------------------
// LIF elementwise update for layers 1..3; also emits ed1 and eg3.
// ---------------------------------------------------------------------------
__global__ void lif_k(float* dout) {
    const long idx = (long)blockIdx.x * blockDim.x + threadIdx.x;
    if (idx >= 3L * S_LAYER) return;
    const int L = (int)(idx / S_LAYER);          // 0..2 -> layers 1..3
    const int r = (int)(idx - (long)L * S_LAYER);

    const float tin = g_tin[idx];
    float j = g_state[idx];
    float v = g_state[3L * S_LAYER + idx];
    float x = g_state[6L * S_LAYER + idx];

    j = j + 0.25f * (tin - j);                    // dt/tau_j = 0.25
    v = v + 0.05f * (j - v);                      // dt/tau_m = 0.05
    const float spk = (v > 1.0f) ? 1.0f : 0.0f;
    v = v * (1.0f - spk);
    x = x * (1.0f - 0.025f) + spk;                // dt/tau_tr = 0.025

    g_state[idx] = j;
    g_state[3L * S_LAYER + idx] = v;
    g_state[6L * S_LAYER + idx] = x;

    if (L == 0) {                                 // ed1 = 0.5*x1 - 0.5*x_data@V0^T
        const int b = r >> 12, f = r & 4095;
        dout[(long)b * OUT_LD + 13312 + f] = 0.5f * x - g_c1h[r];
    } else if (L == 2) {                          // eg3 = 0.5*x3 - 0.5*y@W3^T
        const int b = r >> 12, f = r & 4095;
        dout[(long)b * OUT_LD + 9216 + f] = 0.5f * x - g_c2h[r];
    }
}

__global__ void zero_k(float* dout) {
    const long n1 = 9L * S_LAYER;
    const long n2 = 512L * OUT_LD;
    for (long i = (long)blockIdx.x * blockDim.x + threadIdx.x; i < n1 + n2;
         i += (long)gridDim.x * blockDim.x) {
        if (i < n1) g_state[i] = 0.0f;
        else        dout[i - n1] = 0.0f;
    }
}

// ---------------------------------------------------------------------------
static void gemm2(bool tb,
                  const float* A1, int lda1, const float* B1, int ldb1, int K1,
                  const float* A2, int lda2, const float* B2, int ldb2, int K2,
                  float* C, int ldc,
                  const float* a0, int l0, float g0,
                  const float* a1, int l1, float g1,
                  float alpha, int M, int N,
                  int kc = 0, int nsplit = 1, long czstride = 0) {
    GemmP p;
    p.A1 = A1; p.lda1 = lda1; p.B1 = B1; p.ldb1 = ldb1;
    p.A2 = A2; p.lda2 = lda2; p.B2 = B2; p.ldb2 = ldb2;
    p.K1 = K1; p.K2 = K2;
    p.C = C; p.ldc = ldc;
    p.aux0 = a0; p.ld0 = l0; p.g0 = g0;
    p.aux1 = a1; p.ld1 = l1; p.g1 = g1;
    p.alpha = alpha; p.kc = kc; p.czstride = czstride;
    dim3 grid(N / BN, M / BM, nsplit);
    if (tb) gemm_k<true><<<grid, 256>>>(p);
    else    gemm_k<false><<<grid, 256>>>(p);
}

extern "C" void kernel_launch(void* const* d_in, const int* in_sizes, int n_in,
                              void* d_out, int out_size) {
    (void)in_sizes; (void)n_in; (void)out_size;
    // input order: x_data, y_target, W0, V0, W1, V1, W2, V2, W3, V3, num_steps
    const float* xd = (const float*)d_in[0];   // (512, 1024)
    const float* yt = (const float*)d_in[1];   // (512, 512)
    const float* W0 = (const float*)d_in[2];   // (1024, 4096)
    const float* V0 = (const float*)d_in[3];   // (4096, 1024)
    const float* W1 = (const float*)d_in[4];   // (4096, 4096)
    const float* V1 = (const float*)d_in[5];   // (4096, 4096)
    const float* W2 = (const float*)d_in[6];   // (4096, 4096)
    const float* V2 = (const float*)d_in[7];   // (4096, 4096)
    const float* W3 = (const float*)d_in[8];   // (4096, 512)
    const float* V3 = (const float*)d_in[9];   // (512, 4096)
    float* out = (float*)d_out;                // (512, 26112)

    float *st = nullptr, *tin = nullptr, *c1h = nullptr, *c2h = nullptr;
    float *pA = nullptr, *pB = nullptr;
    cudaGetSymbolAddress((void**)&st,  g_state);
    cudaGetSymbolAddress((void**)&tin, g_tin);
    cudaGetSymbolAddress((void**)&c1h, g_c1h);
    cudaGetSymbolAddress((void**)&c2h, g_c2h);
    cudaGetSymbolAddress((void**)&pA,  g_pA);
    cudaGetSymbolAddress((void**)&pB,  g_pB);

    float* x1 = st + 6L * S_LAYER;
    float* x2 = st + 7L * S_LAYER;
    float* x3 = st + 8L * S_LAYER;
    float* t1 = tin;
    float* t2 = tin + S_LAYER;
    float* t3 = tin + 2L * S_LAYER;

    // error-tensor slices inside d_out (row stride OUT_LD)
    float* eg0 = out + 0;
    float* eg1 = out + 1024;
    float* eg2 = out + 5120;
    float* eg3 = out + 9216;     // written by lif_k
    float* ed1 = out + 13312;    // written by lif_k
    float* ed2 = out + 17408;
    float* ed3 = out + 21504;
    float* ed4 = out + 25600;

    // --- init: zero state + all error signals ---
    zero_k<<<2048, 256>>>(out);

    // --- step-invariant terms ---
    gemm2(true, xd, 1024, V0, 1024, 1024, nullptr, 0, nullptr, 0, 0,
          c1h, 4096, nullptr, 0, 0.f, nullptr, 0, 0.f, 0.5f, 512, 4096);
    gemm2(true, yt, 512, W3, 512, 512, nullptr, 0, nullptr, 0, 0,
          c2h, 4096, nullptr, 0, 0.f, nullptr, 0, 0.f, 0.5f, 512, 4096);

    const int NUM_STEPS = 25;
    for (int t = 0; t < NUM_STEPS; t++) {
        // ---------------- Phase A: injected currents (merged 2-segment K) ----
        // t1 = eg0@W0 + ed2@V1 - ed1 - eg1       (K = 1024 + 4096)
        gemm2(false, eg0, OUT_LD, W0, 4096, 1024,
                     ed2, OUT_LD, V1, 4096, 4096,
              t1, 4096, ed1, OUT_LD, -1.f, eg1, OUT_LD, -1.f, 1.f, 512, 4096);
        // t2 = eg1@W1 + ed3@V2 - ed2 - eg2       (K = 4096 + 4096)
        gemm2(false, eg1, OUT_LD, W1, 4096, 4096,
                     ed3, OUT_LD, V2, 4096, 4096,
              t2, 4096, ed2, OUT_LD, -1.f, eg2, OUT_LD, -1.f, 1.f, 512, 4096);
        // t3 = eg2@W2 + ed4@V3 - ed3 - eg3       (K = 4096 + 512)
        gemm2(false, eg2, OUT_LD, W2, 4096, 4096,
                     ed4, OUT_LD, V3, 4096, 512,
              t3, 4096, ed3, OUT_LD, -1.f, eg3, OUT_LD, -1.f, 1.f, 512, 4096);

        // ---------------- LIF update (+ ed1, eg3) ----------------
        lif_k<<<(3 * S_LAYER + 255) / 256, 256>>>(out);

        // ---------------- Phase B: error signals ----------------
        // eg1 = 0.5*x1 - 0.5*(x2 @ W1^T)
        gemm2(true, x2, 4096, W1, 4096, 4096, nullptr, 0, nullptr, 0, 0,
              eg1, OUT_LD, x1, 4096, 0.5f, nullptr, 0, 0.f, -0.5f, 512, 4096);
        // ed2 = 0.5*x2 - 0.5*(x1 @ V1^T)
        gemm2(true, x1, 4096, V1, 4096, 4096, nullptr, 0, nullptr, 0, 0,
              ed2, OUT_LD, x2, 4096, 0.5f, nullptr, 0, 0.f, -0.5f, 512, 4096);
        // eg2 = 0.5*x2 - 0.5*(x3 @ W2^T)
        gemm2(true, x3, 4096, W2, 4096, 4096, nullptr, 0, nullptr, 0, 0,
              eg2, OUT_LD, x2, 4096, 0.5f, nullptr, 0, 0.f, -0.5f, 512, 4096);
        // ed3 = 0.5*x3 - 0.5*(x2 @ V2^T)
        gemm2(true, x2, 4096, V2, 4096, 4096, nullptr, 0, nullptr, 0, 0,
              ed3, OUT_LD, x3, 4096, 0.5f, nullptr, 0, 0.f, -0.5f, 512, 4096);

        // eg0 = 0.5*x_data - 0.5*(x1 @ W0^T)   split-K 4x (N=1024, K=4096)
        gemm2(true, x1, 4096, W0, 4096, 4096, nullptr, 0, nullptr, 0, 0,
              pA, 1024, nullptr, 0, 0.f, nullptr, 0, 0.f, 1.f, 512, 1024,
              /*kc=*/1024, /*nsplit=*/4, /*czstride=*/(long)512 * 1024);
        reduce_k<<<(512 * 1024 + 255) / 256, 256>>>(pA, 4, xd, 1024, out, 0, 1024);

        // ed4 = 0.5*y - 0.5*(x3 @ V3^T)        split-K 8x (N=512, K=4096)
        gemm2(true, x3, 4096, V3, 4096, 4096, nullptr, 0, nullptr, 0, 0,
              pB, 512, nullptr, 0, 0.f, nullptr, 0, 0.f, 1.f, 512, 512,
              /*kc=*/512, /*nsplit=*/8, /*czstride=*/(long)512 * 512);
        reduce_k<<<(512 * 512 + 255) / 256, 256>>>(pB, 8, yt, 512, out, 25600, 512);
    }
}